// round 2
// baseline (speedup 1.0000x reference)
#include <cuda_runtime.h>
#include <math.h>

// Problem constants
#define BB 4
#define NN_ 1024
#define CC 1024
#define HH 16
#define HD_ 64
#define M_ROWS (BB * NN_)        // 4096
#define QKV_COLS (3 * CC)        // 3072

// Scratch (device globals: allocation-free)
__device__ float g_qkv[(size_t)M_ROWS * QKV_COLS];   // 48 MB
__device__ float g_ctx[(size_t)M_ROWS * CC];         // 16 MB

// ---------------------------------------------------------------------------
// Generic NN GEMM with optional bias: C[M,N] = A[M,K] @ B[K,N] + bias[N]
// BM=BN=64, BK=16, 256 threads, 4x4 per thread. Dims must divide tiles.
// ---------------------------------------------------------------------------
__global__ void gemm_nn_bias(const float* __restrict__ A,
                             const float* __restrict__ B,
                             const float* __restrict__ bias,
                             float* __restrict__ C,
                             int M, int N, int K) {
    const int BM = 64, BN = 64, BK = 16, TM = 4, TN = 4;
    __shared__ float As[BM][BK + 1];
    __shared__ float Bs[BK][BN + 1];

    int tx = threadIdx.x % (BN / TN);   // 0..15
    int ty = threadIdx.x / (BN / TN);   // 0..15
    int row0 = blockIdx.y * BM;
    int col0 = blockIdx.x * BN;

    float acc[TM][TN];
#pragma unroll
    for (int i = 0; i < TM; i++)
#pragma unroll
        for (int j = 0; j < TN; j++) acc[i][j] = 0.0f;

    for (int k0 = 0; k0 < K; k0 += BK) {
        for (int i = threadIdx.x; i < BM * BK; i += 256) {
            int r = i / BK, c = i % BK;
            As[r][c] = A[(size_t)(row0 + r) * K + k0 + c];
        }
        for (int i = threadIdx.x; i < BK * BN; i += 256) {
            int r = i / BN, c = i % BN;
            Bs[r][c] = B[(size_t)(k0 + r) * N + col0 + c];
        }
        __syncthreads();
#pragma unroll
        for (int kk = 0; kk < BK; kk++) {
            float a[TM], b[TN];
#pragma unroll
            for (int i = 0; i < TM; i++) a[i] = As[ty * TM + i][kk];
#pragma unroll
            for (int j = 0; j < TN; j++) b[j] = Bs[kk][tx * TN + j];
#pragma unroll
            for (int i = 0; i < TM; i++)
#pragma unroll
                for (int j = 0; j < TN; j++) acc[i][j] += a[i] * b[j];
        }
        __syncthreads();
    }

#pragma unroll
    for (int i = 0; i < TM; i++) {
        int r = row0 + ty * TM + i;
#pragma unroll
        for (int j = 0; j < TN; j++) {
            int c = col0 + tx * TN + j;
            float v = acc[i][j];
            if (bias) v += bias[c];
            C[(size_t)r * N + c] = v;
        }
    }
}

// ---------------------------------------------------------------------------
// Scores: per (b,h), S[n,m] = scale * Q[n,:]·K[m,:] + int_matrix + (1-mask)*-1e9
// Q/K live inside g_qkv with row stride 3072. NT GEMM, K=64.
// ---------------------------------------------------------------------------
__global__ void scores_kernel(const float* __restrict__ intm,
                              const float* __restrict__ mask,
                              float* __restrict__ attn) {
    const int BK = 16, TM = 4, TN = 4;
    int bh = blockIdx.z;
    int b = bh >> 4;           // / HH
    // int h = bh & 15;
    const float* Q = g_qkv + (size_t)b * NN_ * QKV_COLS + (bh & 15) * HD_;
    const float* Kp = g_qkv + (size_t)b * NN_ * QKV_COLS + CC + (bh & 15) * HD_;

    __shared__ float Qs[64][BK + 1];
    __shared__ float Ks[64][BK + 1];

    int tx = threadIdx.x % 16;
    int ty = threadIdx.x / 16;
    int n0 = blockIdx.y * 64;
    int m0 = blockIdx.x * 64;

    float acc[TM][TN];
#pragma unroll
    for (int i = 0; i < TM; i++)
#pragma unroll
        for (int j = 0; j < TN; j++) acc[i][j] = 0.0f;

    for (int k0 = 0; k0 < HD_; k0 += BK) {
        for (int i = threadIdx.x; i < 64 * BK; i += 256) {
            int r = i / BK, c = i % BK;
            Qs[r][c] = Q[(size_t)(n0 + r) * QKV_COLS + k0 + c];
            Ks[r][c] = Kp[(size_t)(m0 + r) * QKV_COLS + k0 + c];
        }
        __syncthreads();
#pragma unroll
        for (int kk = 0; kk < BK; kk++) {
            float a[TM], bv[TN];
#pragma unroll
            for (int i = 0; i < TM; i++) a[i] = Qs[ty * TM + i][kk];
#pragma unroll
            for (int j = 0; j < TN; j++) bv[j] = Ks[tx * TN + j][kk];
#pragma unroll
            for (int i = 0; i < TM; i++)
#pragma unroll
                for (int j = 0; j < TN; j++) acc[i][j] += a[i] * bv[j];
        }
        __syncthreads();
    }

    const float scale = 0.125f;  // 64^-0.5
#pragma unroll
    for (int i = 0; i < TM; i++) {
        int n = n0 + ty * TM + i;
#pragma unroll
        for (int j = 0; j < TN; j++) {
            int m = m0 + tx * TN + j;
            size_t aidx = ((size_t)bh * NN_ + n) * NN_ + m;
            size_t midx = ((size_t)b * NN_ + n) * NN_ + m;   // mask broadcasts over heads
            float s = scale * acc[i][j] + intm[aidx] + (1.0f - mask[midx]) * (-1e9f);
            attn[aidx] = s;
        }
    }
}

// ---------------------------------------------------------------------------
// Row softmax, in-place on the attn region. One block per row (256 thr, 4/thr)
// ---------------------------------------------------------------------------
__global__ void softmax_kernel(float* __restrict__ attn) {
    __shared__ float shm[8];
    __shared__ float shs[8];
    __shared__ float bcast;

    size_t row = blockIdx.x;
    float* p = attn + row * NN_;
    int t = threadIdx.x;
    int lane = t & 31, wid = t >> 5;

    float v[4];
    float mx = -1e30f;
#pragma unroll
    for (int i = 0; i < 4; i++) {
        v[i] = p[t + 256 * i];
        mx = fmaxf(mx, v[i]);
    }
    // block max
#pragma unroll
    for (int o = 16; o > 0; o >>= 1) mx = fmaxf(mx, __shfl_xor_sync(0xffffffffu, mx, o));
    if (lane == 0) shm[wid] = mx;
    __syncthreads();
    if (wid == 0) {
        float m2 = (lane < 8) ? shm[lane] : -1e30f;
#pragma unroll
        for (int o = 4; o > 0; o >>= 1) m2 = fmaxf(m2, __shfl_xor_sync(0xffffffffu, m2, o));
        if (lane == 0) bcast = m2;
    }
    __syncthreads();
    mx = bcast;

    float s = 0.0f;
#pragma unroll
    for (int i = 0; i < 4; i++) {
        v[i] = __expf(v[i] - mx);
        s += v[i];
    }
#pragma unroll
    for (int o = 16; o > 0; o >>= 1) s += __shfl_xor_sync(0xffffffffu, s, o);
    if (lane == 0) shs[wid] = s;
    __syncthreads();
    if (wid == 0) {
        float s2 = (lane < 8) ? shs[lane] : 0.0f;
#pragma unroll
        for (int o = 4; o > 0; o >>= 1) s2 += __shfl_xor_sync(0xffffffffu, s2, o);
        if (lane == 0) bcast = s2;
    }
    __syncthreads();
    float inv = 1.0f / bcast;
#pragma unroll
    for (int i = 0; i < 4; i++) p[t + 256 * i] = v[i] * inv;
}

// ---------------------------------------------------------------------------
// ctx = attn @ V per (b,h). A [1024,1024] row-major, V rows stride 3072.
// Output layout [b, n, h, hd] -> g_ctx[(b*N+n)*C + h*64 + d]
// ---------------------------------------------------------------------------
__global__ void ctx_kernel(const float* __restrict__ attn) {
    const int BK = 16, TM = 4, TN = 4;
    int bh = blockIdx.z;
    int b = bh >> 4;
    int h = bh & 15;
    const float* A = attn + (size_t)bh * NN_ * NN_;
    const float* V = g_qkv + (size_t)b * NN_ * QKV_COLS + 2 * CC + h * HD_;

    __shared__ float As[64][BK + 1];
    __shared__ float Vs[BK][64 + 1];

    int tx = threadIdx.x % 16;
    int ty = threadIdx.x / 16;
    int n0 = blockIdx.y * 64;   // d covered fully by BN=64

    float acc[TM][TN];
#pragma unroll
    for (int i = 0; i < TM; i++)
#pragma unroll
        for (int j = 0; j < TN; j++) acc[i][j] = 0.0f;

    for (int k0 = 0; k0 < NN_; k0 += BK) {
        for (int i = threadIdx.x; i < 64 * BK; i += 256) {
            int r = i / BK, c = i % BK;
            As[r][c] = A[(size_t)(n0 + r) * NN_ + k0 + c];
        }
        for (int i = threadIdx.x; i < BK * 64; i += 256) {
            int r = i / 64, c = i % 64;
            Vs[r][c] = V[(size_t)(k0 + r) * QKV_COLS + c];
        }
        __syncthreads();
#pragma unroll
        for (int kk = 0; kk < BK; kk++) {
            float a[TM], bv[TN];
#pragma unroll
            for (int i = 0; i < TM; i++) a[i] = As[ty * TM + i][kk];
#pragma unroll
            for (int j = 0; j < TN; j++) bv[j] = Vs[kk][tx * TN + j];
#pragma unroll
            for (int i = 0; i < TM; i++)
#pragma unroll
                for (int j = 0; j < TN; j++) acc[i][j] += a[i] * bv[j];
        }
        __syncthreads();
    }

#pragma unroll
    for (int i = 0; i < TM; i++) {
        int n = n0 + ty * TM + i;
#pragma unroll
        for (int j = 0; j < TN; j++) {
            int d = tx * TN + j;
            g_ctx[((size_t)b * NN_ + n) * CC + h * HD_ + d] = acc[i][j];
        }
    }
}

// ---------------------------------------------------------------------------
extern "C" void kernel_launch(void* const* d_in, const int* in_sizes, int n_in,
                              void* d_out, int out_size) {
    const float* x     = (const float*)d_in[0];
    const float* intm  = (const float*)d_in[1];
    const float* mask  = (const float*)d_in[2];
    const float* Wqkv  = (const float*)d_in[3];
    const float* bqkv  = (const float*)d_in[4];
    const float* Wproj = (const float*)d_in[5];
    const float* bproj = (const float*)d_in[6];

    float* out  = (float*)d_out;                        // [4,1024,1024]
    float* attn = out + (size_t)BB * NN_ * CC;          // [4,16,1024,1024]

    float* qkv_ptr = nullptr;
    float* ctx_ptr = nullptr;
    cudaGetSymbolAddress((void**)&qkv_ptr, g_qkv);
    cudaGetSymbolAddress((void**)&ctx_ptr, g_ctx);

    // 1. qkv = x @ W_qkv + b_qkv  (M=4096, N=3072, K=1024)
    gemm_nn_bias<<<dim3(QKV_COLS / 64, M_ROWS / 64), 256>>>(
        x, Wqkv, bqkv, qkv_ptr, M_ROWS, QKV_COLS, CC);

    // 2. scores (+int_matrix, +mask) -> attn region of d_out
    scores_kernel<<<dim3(NN_ / 64, NN_ / 64, BB * HH), 256>>>(intm, mask, attn);

    // 3. softmax in-place
    softmax_kernel<<<BB * HH * NN_, 256>>>(attn);

    // 4. ctx = attn @ V
    ctx_kernel<<<dim3(1, NN_ / 64, BB * HH), 256>>>(attn);

    // 5. out = ctx @ W_proj + b_proj  (M=4096, N=1024, K=1024)
    gemm_nn_bias<<<dim3(CC / 64, M_ROWS / 64), 256>>>(
        ctx_ptr, Wproj, bproj, out, M_ROWS, CC, CC);
}

// round 3
// speedup vs baseline: 3.2599x; 3.2599x over previous
#include <cuda_runtime.h>
#include <stdint.h>
#include <math.h>

#define BB 4
#define NN_ 1024
#define CC 1024
#define HH 16
#define HD_ 64
#define M_ROWS (BB * NN_)        // 4096
#define QKV_COLS (3 * CC)        // 3072

__device__ float g_qkv[(size_t)M_ROWS * QKV_COLS];   // 48 MB
__device__ float g_ctx[(size_t)M_ROWS * CC];         // 16 MB

// ---------------------------------------------------------------------------
// tf32 helpers
// ---------------------------------------------------------------------------
__device__ __forceinline__ uint32_t f2tf(float f) {
    uint32_t r;
    asm("cvt.rna.tf32.f32 %0, %1;" : "=r"(r) : "f"(f));
    return r;
}

__device__ __forceinline__ void mma8(float* d, const uint32_t* a, const uint32_t* b) {
    asm volatile(
        "mma.sync.aligned.m16n8k8.row.col.f32.tf32.tf32.f32 "
        "{%0,%1,%2,%3}, {%4,%5,%6,%7}, {%8,%9}, {%0,%1,%2,%3};"
        : "+f"(d[0]), "+f"(d[1]), "+f"(d[2]), "+f"(d[3])
        : "r"(a[0]), "r"(a[1]), "r"(a[2]), "r"(a[3]), "r"(b[0]), "r"(b[1]));
}

// ---------------------------------------------------------------------------
// Generic NN GEMM + bias, tf32 MMA. C[M,N] = A[M,K] @ B[K,N] + bias[N]
// Block tile 128x128x16, 256 threads (8 warps, warp tile 32x64).
// ---------------------------------------------------------------------------
__global__ __launch_bounds__(256) void gemm_tf32_bias(
    const float* __restrict__ A, const float* __restrict__ B,
    const float* __restrict__ bias, float* __restrict__ C,
    int M, int N, int K, int lda, int ldb, int ldc) {

    __shared__ uint32_t As[16][136];   // [k][m], tf32 bits
    __shared__ uint32_t Bs[16][136];   // [k][n], tf32 bits

    const int tid  = threadIdx.x;
    const int lane = tid & 31;
    const int w    = tid >> 5;
    const int wm   = w & 3;            // 0..3  -> m block of 32
    const int wn   = w >> 2;           // 0..1  -> n block of 64
    const int row0 = blockIdx.y * 128;
    const int col0 = blockIdx.x * 128;
    const int m_base = wm * 32;
    const int n_base = wn * 64;
    const int lr = lane >> 2;          // 0..7
    const int lc = lane & 3;           // 0..3

    float acc[2][8][4];
#pragma unroll
    for (int i = 0; i < 2; i++)
#pragma unroll
        for (int j = 0; j < 8; j++)
#pragma unroll
            for (int t = 0; t < 4; t++) acc[i][j][t] = 0.0f;

    for (int k0 = 0; k0 < K; k0 += 16) {
        // load A tile: 128 rows x 16 k (512 float4)
#pragma unroll
        for (int it = 0; it < 2; it++) {
            int i = tid + it * 256;
            int r = i >> 2, kq = (i & 3) * 4;
            float4 v = *(const float4*)&A[(size_t)(row0 + r) * lda + k0 + kq];
            As[kq + 0][r] = f2tf(v.x);
            As[kq + 1][r] = f2tf(v.y);
            As[kq + 2][r] = f2tf(v.z);
            As[kq + 3][r] = f2tf(v.w);
        }
        // load B tile: 16 k x 128 n (512 float4)
#pragma unroll
        for (int it = 0; it < 2; it++) {
            int i = tid + it * 256;
            int kk = i >> 5, nq = (i & 31) * 4;
            float4 v = *(const float4*)&B[(size_t)(k0 + kk) * ldb + col0 + nq];
            Bs[kk][nq + 0] = f2tf(v.x);
            Bs[kk][nq + 1] = f2tf(v.y);
            Bs[kk][nq + 2] = f2tf(v.z);
            Bs[kk][nq + 3] = f2tf(v.w);
        }
        __syncthreads();

#pragma unroll
        for (int ks = 0; ks < 16; ks += 8) {
            uint32_t a[2][4], b[8][2];
#pragma unroll
            for (int im = 0; im < 2; im++) {
                int m0 = m_base + im * 16;
                a[im][0] = As[ks + lc][m0 + lr];
                a[im][1] = As[ks + lc][m0 + 8 + lr];
                a[im][2] = As[ks + 4 + lc][m0 + lr];
                a[im][3] = As[ks + 4 + lc][m0 + 8 + lr];
            }
#pragma unroll
            for (int in = 0; in < 8; in++) {
                int n0 = n_base + in * 8;
                b[in][0] = Bs[ks + lc][n0 + lr];
                b[in][1] = Bs[ks + 4 + lc][n0 + lr];
            }
#pragma unroll
            for (int im = 0; im < 2; im++)
#pragma unroll
                for (int in = 0; in < 8; in++)
                    mma8(acc[im][in], a[im], b[in]);
        }
        __syncthreads();
    }

    // epilogue
#pragma unroll
    for (int im = 0; im < 2; im++) {
#pragma unroll
        for (int in = 0; in < 8; in++) {
            int r0 = row0 + m_base + im * 16 + lr;
            int c0 = col0 + n_base + in * 8 + lc * 2;
            float b0 = bias ? bias[c0] : 0.0f;
            float b1 = bias ? bias[c0 + 1] : 0.0f;
            C[(size_t)r0 * ldc + c0]         = acc[im][in][0] + b0;
            C[(size_t)r0 * ldc + c0 + 1]     = acc[im][in][1] + b1;
            C[(size_t)(r0 + 8) * ldc + c0]     = acc[im][in][2] + b0;
            C[(size_t)(r0 + 8) * ldc + c0 + 1] = acc[im][in][3] + b1;
        }
    }
}

// ---------------------------------------------------------------------------
// Scores: per (b,h), S[n,m] = 0.125*Q[n,:]·K[m,:] + int_matrix + (1-mask)*-1e9
// Q rows stride 3072; K transposed into B layout at smem store.
// Block tile 128x128, K=64.
// ---------------------------------------------------------------------------
__global__ __launch_bounds__(256) void scores_tf32(
    const float* __restrict__ intm, const float* __restrict__ mask,
    float* __restrict__ attn) {

    __shared__ uint32_t As[16][136];   // [k][n-of-Q]
    __shared__ uint32_t Bs[16][136];   // [k][m-of-K]

    const int tid  = threadIdx.x;
    const int lane = tid & 31;
    const int w    = tid >> 5;
    const int wm   = w & 3;
    const int wn   = w >> 2;
    const int bh = blockIdx.z;
    const int b  = bh >> 4;
    const int h  = bh & 15;
    const float* Q  = g_qkv + (size_t)b * NN_ * QKV_COLS + h * HD_;
    const float* Kp = g_qkv + (size_t)b * NN_ * QKV_COLS + CC + h * HD_;

    const int row0 = blockIdx.y * 128;   // n
    const int col0 = blockIdx.x * 128;   // m
    const int m_base = wm * 32;
    const int n_base = wn * 64;
    const int lr = lane >> 2;
    const int lc = lane & 3;

    float acc[2][8][4];
#pragma unroll
    for (int i = 0; i < 2; i++)
#pragma unroll
        for (int j = 0; j < 8; j++)
#pragma unroll
            for (int t = 0; t < 4; t++) acc[i][j][t] = 0.0f;

    for (int k0 = 0; k0 < HD_; k0 += 16) {
#pragma unroll
        for (int it = 0; it < 2; it++) {
            int i = tid + it * 256;
            int r = i >> 2, kq = (i & 3) * 4;
            float4 v = *(const float4*)&Q[(size_t)(row0 + r) * QKV_COLS + k0 + kq];
            As[kq + 0][r] = f2tf(v.x);
            As[kq + 1][r] = f2tf(v.y);
            As[kq + 2][r] = f2tf(v.z);
            As[kq + 3][r] = f2tf(v.w);
            float4 u = *(const float4*)&Kp[(size_t)(col0 + r) * QKV_COLS + k0 + kq];
            Bs[kq + 0][r] = f2tf(u.x);
            Bs[kq + 1][r] = f2tf(u.y);
            Bs[kq + 2][r] = f2tf(u.z);
            Bs[kq + 3][r] = f2tf(u.w);
        }
        __syncthreads();

#pragma unroll
        for (int ks = 0; ks < 16; ks += 8) {
            uint32_t a[2][4], bfrag[8][2];
#pragma unroll
            for (int im = 0; im < 2; im++) {
                int m0 = m_base + im * 16;
                a[im][0] = As[ks + lc][m0 + lr];
                a[im][1] = As[ks + lc][m0 + 8 + lr];
                a[im][2] = As[ks + 4 + lc][m0 + lr];
                a[im][3] = As[ks + 4 + lc][m0 + 8 + lr];
            }
#pragma unroll
            for (int in = 0; in < 8; in++) {
                int n0 = n_base + in * 8;
                bfrag[in][0] = Bs[ks + lc][n0 + lr];
                bfrag[in][1] = Bs[ks + 4 + lc][n0 + lr];
            }
#pragma unroll
            for (int im = 0; im < 2; im++)
#pragma unroll
                for (int in = 0; in < 8; in++)
                    mma8(acc[im][in], a[im], bfrag[in]);
        }
        __syncthreads();
    }

    const float scale = 0.125f;
#pragma unroll
    for (int im = 0; im < 2; im++) {
#pragma unroll
        for (int in = 0; in < 8; in++) {
#pragma unroll
            for (int half = 0; half < 2; half++) {
                int n = row0 + m_base + im * 16 + lr + half * 8;
                int m = col0 + n_base + in * 8 + lc * 2;
                size_t aidx = ((size_t)bh * NN_ + n) * NN_ + m;
                size_t midx = ((size_t)b * NN_ + n) * NN_ + m;
                float s0 = scale * acc[im][in][half * 2]     + intm[aidx]
                           + (1.0f - mask[midx]) * (-1e9f);
                float s1 = scale * acc[im][in][half * 2 + 1] + intm[aidx + 1]
                           + (1.0f - mask[midx + 1]) * (-1e9f);
                attn[aidx]     = s0;
                attn[aidx + 1] = s1;
            }
        }
    }
}

// ---------------------------------------------------------------------------
// Row softmax, in-place. One block per row.
// ---------------------------------------------------------------------------
__global__ void softmax_kernel(float* __restrict__ attn) {
    __shared__ float shm[8];
    __shared__ float shs[8];
    __shared__ float bcast;

    size_t row = blockIdx.x;
    float* p = attn + row * NN_;
    int t = threadIdx.x;
    int lane = t & 31, wid = t >> 5;

    float v[4];
    float mx = -1e30f;
#pragma unroll
    for (int i = 0; i < 4; i++) {
        v[i] = p[t + 256 * i];
        mx = fmaxf(mx, v[i]);
    }
#pragma unroll
    for (int o = 16; o > 0; o >>= 1) mx = fmaxf(mx, __shfl_xor_sync(0xffffffffu, mx, o));
    if (lane == 0) shm[wid] = mx;
    __syncthreads();
    if (wid == 0) {
        float m2 = (lane < 8) ? shm[lane] : -1e30f;
#pragma unroll
        for (int o = 4; o > 0; o >>= 1) m2 = fmaxf(m2, __shfl_xor_sync(0xffffffffu, m2, o));
        if (lane == 0) bcast = m2;
    }
    __syncthreads();
    mx = bcast;

    float s = 0.0f;
#pragma unroll
    for (int i = 0; i < 4; i++) {
        v[i] = __expf(v[i] - mx);
        s += v[i];
    }
#pragma unroll
    for (int o = 16; o > 0; o >>= 1) s += __shfl_xor_sync(0xffffffffu, s, o);
    if (lane == 0) shs[wid] = s;
    __syncthreads();
    if (wid == 0) {
        float s2 = (lane < 8) ? shs[lane] : 0.0f;
#pragma unroll
        for (int o = 4; o > 0; o >>= 1) s2 += __shfl_xor_sync(0xffffffffu, s2, o);
        if (lane == 0) bcast = s2;
    }
    __syncthreads();
    float inv = 1.0f / bcast;
#pragma unroll
    for (int i = 0; i < 4; i++) p[t + 256 * i] = v[i] * inv;
}

// ---------------------------------------------------------------------------
// ctx = attn @ V per (b,h). Block tile 128x64, 8 warps each 16x64.
// Output [b, n, h, hd] layout into g_ctx.
// ---------------------------------------------------------------------------
__global__ __launch_bounds__(256) void ctx_tf32(const float* __restrict__ attn) {
    __shared__ uint32_t As[16][136];  // [k][n]  (k = m-index of attn)
    __shared__ uint32_t Bs[16][72];   // [k][d]

    const int tid  = threadIdx.x;
    const int lane = tid & 31;
    const int w    = tid >> 5;
    const int bh = blockIdx.z;
    const int b  = bh >> 4;
    const int h  = bh & 15;
    const float* A = attn + (size_t)bh * NN_ * NN_;
    const float* V = g_qkv + (size_t)b * NN_ * QKV_COLS + 2 * CC + h * HD_;

    const int row0 = blockIdx.y * 128;
    const int m_base = w * 16;
    const int lr = lane >> 2;
    const int lc = lane & 3;

    float acc[8][4];
#pragma unroll
    for (int j = 0; j < 8; j++)
#pragma unroll
        for (int t = 0; t < 4; t++) acc[j][t] = 0.0f;

    for (int k0 = 0; k0 < NN_; k0 += 16) {
#pragma unroll
        for (int it = 0; it < 2; it++) {
            int i = tid + it * 256;
            int r = i >> 2, kq = (i & 3) * 4;
            float4 v = *(const float4*)&A[(size_t)(row0 + r) * NN_ + k0 + kq];
            As[kq + 0][r] = f2tf(v.x);
            As[kq + 1][r] = f2tf(v.y);
            As[kq + 2][r] = f2tf(v.z);
            As[kq + 3][r] = f2tf(v.w);
        }
        {
            int kk = tid >> 4, nq = (tid & 15) * 4;
            float4 v = *(const float4*)&V[(size_t)(k0 + kk) * QKV_COLS + nq];
            Bs[kk][nq + 0] = f2tf(v.x);
            Bs[kk][nq + 1] = f2tf(v.y);
            Bs[kk][nq + 2] = f2tf(v.z);
            Bs[kk][nq + 3] = f2tf(v.w);
        }
        __syncthreads();

#pragma unroll
        for (int ks = 0; ks < 16; ks += 8) {
            uint32_t a[4], bfrag[8][2];
            a[0] = As[ks + lc][m_base + lr];
            a[1] = As[ks + lc][m_base + 8 + lr];
            a[2] = As[ks + 4 + lc][m_base + lr];
            a[3] = As[ks + 4 + lc][m_base + 8 + lr];
#pragma unroll
            for (int in = 0; in < 8; in++) {
                int n0 = in * 8;
                bfrag[in][0] = Bs[ks + lc][n0 + lr];
                bfrag[in][1] = Bs[ks + 4 + lc][n0 + lr];
            }
#pragma unroll
            for (int in = 0; in < 8; in++)
                mma8(acc[in], a, bfrag[in]);
        }
        __syncthreads();
    }

#pragma unroll
    for (int in = 0; in < 8; in++) {
#pragma unroll
        for (int half = 0; half < 2; half++) {
            int n = row0 + m_base + lr + half * 8;
            int d = in * 8 + lc * 2;
            size_t idx = ((size_t)b * NN_ + n) * CC + h * HD_ + d;
            g_ctx[idx]     = acc[in][half * 2];
            g_ctx[idx + 1] = acc[in][half * 2 + 1];
        }
    }
}

// ---------------------------------------------------------------------------
extern "C" void kernel_launch(void* const* d_in, const int* in_sizes, int n_in,
                              void* d_out, int out_size) {
    const float* x     = (const float*)d_in[0];
    const float* intm  = (const float*)d_in[1];
    const float* mask  = (const float*)d_in[2];
    const float* Wqkv  = (const float*)d_in[3];
    const float* bqkv  = (const float*)d_in[4];
    const float* Wproj = (const float*)d_in[5];
    const float* bproj = (const float*)d_in[6];

    float* out  = (float*)d_out;                        // [4,1024,1024]
    float* attn = out + (size_t)BB * NN_ * CC;          // [4,16,1024,1024]

    float* qkv_ptr = nullptr;
    float* ctx_ptr = nullptr;
    cudaGetSymbolAddress((void**)&qkv_ptr, g_qkv);
    cudaGetSymbolAddress((void**)&ctx_ptr, g_ctx);

    // 1. qkv = x @ W_qkv + b_qkv   (M=4096, N=3072, K=1024)
    gemm_tf32_bias<<<dim3(QKV_COLS / 128, M_ROWS / 128), 256>>>(
        x, Wqkv, bqkv, qkv_ptr, M_ROWS, QKV_COLS, CC, CC, QKV_COLS, QKV_COLS);

    // 2. scores -> attn region of d_out
    scores_tf32<<<dim3(NN_ / 128, NN_ / 128, BB * HH), 256>>>(intm, mask, attn);

    // 3. softmax in-place
    softmax_kernel<<<BB * HH * NN_, 256>>>(attn);

    // 4. ctx = attn @ V
    ctx_tf32<<<dim3(1, NN_ / 128, BB * HH), 256>>>(attn);

    // 5. out = ctx @ W_proj + b_proj   (M=4096, N=1024, K=1024)
    gemm_tf32_bias<<<dim3(CC / 128, M_ROWS / 128), 256>>>(
        ctx_ptr, Wproj, bproj, out, M_ROWS, CC, CC, CC, CC, CC);
}